// round 4
// baseline (speedup 1.0000x reference)
#include <cuda_runtime.h>
#include <cstdint>

// UpsampleLayer2D quadrant depth-to-space:
// out[b, r2, c2, co] = x[b, r2%R, c2%C, 4*co + k],  k = 2*(r2>=R) + (c2>=C)
// B=32, R=C=200, Cin=64, Co=16.
//
// R4: persistent grid-stride version of the R1 kernel (best DRAM%=83.8).
// Grid sized exactly to residency (148 SMs x 8 blocks x 256 thr, <=32 regs via
// launch_bounds) so there are no wave transitions and no short-block tail --
// the only remaining identified source of DRAM idle (~10% vs 8TB/s floor).
// Body identical to R1: 4 front-batched LDG.128 (warp reads 2KB contiguous),
// 4x4 register transpose, 4 STG.128 (warp writes 512B contiguous per quadrant).

static constexpr int B  = 32;
static constexpr int R  = 200;
static constexpr int C  = 200;
static constexpr int CO = 16;                       // output channels
static constexpr unsigned PIX = B * R * C;          // 1,280,000 pixels
static constexpr unsigned NWORK = PIX * 4;          // 5,120,000 work items

static constexpr unsigned NSM      = 148;
static constexpr unsigned BLK_PER  = 8;
static constexpr unsigned NBLOCKS  = NSM * BLK_PER;     // 1184
static constexpr unsigned NTHREADS = NBLOCKS * 256;     // 303,104 (stride)

// float4 strides in the output [B, 2R, 2C, CO]:
static constexpr size_t OUT_ROW_F4  = (size_t)(2 * C) * CO / 4;   // 1600
static constexpr size_t Q_COL_OFF   = (size_t)C * CO / 4;         // 800
static constexpr size_t Q_ROW_OFF   = (size_t)R * OUT_ROW_F4;     // 320000

__global__ __launch_bounds__(256, 8) void upsample2d_kernel(
    const float4* __restrict__ x4, float4* __restrict__ out4)
{
    unsigned g0 = blockIdx.x * 256u + threadIdx.x;

    for (unsigned g = g0; g < NWORK; g += NTHREADS) {
        unsigned co4 = g & 3u;          // group of 4 output channels
        unsigned pix = g >> 2;          // input pixel index

        unsigned c  = pix % (unsigned)C;
        unsigned rb = pix / (unsigned)C;
        unsigned r  = rb % (unsigned)R;
        unsigned b  = rb / (unsigned)R;

        const float4* src = x4 + (size_t)pix * 16 + (size_t)co4 * 4;
        float4 v0 = __ldcs(src + 0);
        float4 v1 = __ldcs(src + 1);
        float4 v2 = __ldcs(src + 2);
        float4 v3 = __ldcs(src + 3);

        size_t opix = ((size_t)b * (2 * R) + r) * (2 * C) + c;  // quadrant-0 pixel
        size_t o0   = opix * 4 + co4;                            // float4 index

        __stcs(out4 + o0,                         make_float4(v0.x, v1.x, v2.x, v3.x)); // TL
        __stcs(out4 + o0 + Q_COL_OFF,             make_float4(v0.y, v1.y, v2.y, v3.y)); // TR
        __stcs(out4 + o0 + Q_ROW_OFF,             make_float4(v0.z, v1.z, v2.z, v3.z)); // BL
        __stcs(out4 + o0 + Q_ROW_OFF + Q_COL_OFF, make_float4(v0.w, v1.w, v2.w, v3.w)); // BR
    }
}

extern "C" void kernel_launch(void* const* d_in, const int* in_sizes, int n_in,
                              void* d_out, int out_size)
{
    const float4* x4   = (const float4*)d_in[0];
    float4*       out4 = (float4*)d_out;

    upsample2d_kernel<<<NBLOCKS, 256>>>(x4, out4);
}